// round 11
// baseline (speedup 1.0000x reference)
#include <cuda_runtime.h>
#include <cuda_bf16.h>

// GCN: out = log_softmax( GCN2( relu(GCN1(x)) ) )
// GCN_k(z) = Agg(z) @ Wk + bk, Agg = D^-1/2 (A+I) D^-1/2. Aggregation is
// linear, so it commutes with the right-multiply: we aggregate 2-feature
// vectors in BOTH layers (layer2 down-projects t = relu(.)@W2 BEFORE the
// scatter). Edge passes therefore move only float2 per edge.
//
// The harness may deliver the int64 edge_index as int32; a detect kernel
// probes the layout at runtime (odd 32-bit words all-zero <=> int64) and the
// edge kernels branch on the uniform flag.
//
// Pipeline (8 kernels, graph-capturable, allocation-free):
//   K-1 detect idx dtype
//   K0 zero deg -> K1 in-degree -> K2 dinv + layer1 self-loop init
//   K3 edge scatter layer1 (feat = x)
//   K4 node: t = relu(agg@W1+b1)@W2 ; re-seed agg with t self-loop
//   K5 edge scatter layer2 (feat = t)
//   K6 out = log_softmax(agg + b2)

#define MAXN 100352   // N_NODES = 100000, padded

__device__ int      g_idx64;      // 1 if edge index is int64, 0 if int32
__device__ unsigned g_deg[MAXN];
__device__ float    g_dinv[MAXN];
__device__ float2   g_agg[MAXN];
__device__ float2   g_t[MAXN];

__device__ __forceinline__ void red_add_v2(float2* addr, float a, float b) {
    // sm_90+ vector float reduction, fire-and-forget (no L2 return trip)
    asm volatile("red.global.add.v2.f32 [%0], {%1, %2};"
                 :: "l"(addr), "f"(a), "f"(b) : "memory");
}

// Probe: sample 64 odd 32-bit words spread over the first n32 words (safe
// under both interpretations). int64 indices < 2^31 => all high halves 0.
__global__ void k_detect(const int* __restrict__ ei32, long long n32) {
    if (threadIdx.x == 0 && blockIdx.x == 0) {
        long long stride = n32 / 128;           // 64 samples * 2
        int all_zero = 1;
        for (int k = 0; k < 64; k++) {
            long long pos = 2 * (long long)k * stride + 1;
            if (pos < n32 && ei32[pos] != 0) { all_zero = 0; break; }
        }
        g_idx64 = all_zero;
    }
}

__device__ __forceinline__ int edge_idx(const void* ei, long long pos) {
    if (g_idx64) return (int)((const long long*)ei)[pos];
    return ((const int*)ei)[pos];
}

__global__ void k_zero_deg(int n) {
    int v = blockIdx.x * blockDim.x + threadIdx.x;
    if (v < n) g_deg[v] = 0u;
}

// In-degree at dst nodes (dst row = positions [E, 2E)).
__global__ void k_deg(const void* __restrict__ ei, long long E) {
    long long e = (long long)blockIdx.x * blockDim.x + threadIdx.x;
    if (e < E) {
        int d = edge_idx(ei, E + e);
        atomicAdd(&g_deg[d], 1u);
    }
}

// dinv = rsqrt(indeg + 1); seed agg with the layer-1 self-loop term x[v]*dinv^2
__global__ void k_dinv_init(const float2* __restrict__ x, int n) {
    int v = blockIdx.x * blockDim.x + threadIdx.x;
    if (v < n) {
        float dv = rsqrtf((float)(g_deg[v] + 1u));
        g_dinv[v] = dv;
        float2 xv = x[v];
        float w = dv * dv;
        g_agg[v] = make_float2(xv.x * w, xv.y * w);
    }
}

// Edge scatter: agg[dst] += feat[src] * dinv[src] * dinv[dst]
// USE_T=false: feat = input x; USE_T=true: feat = g_t.
template <bool USE_T>
__global__ void k_edge(const void* __restrict__ ei,
                       const float2* __restrict__ feat, long long E) {
    long long e = (long long)blockIdx.x * blockDim.x + threadIdx.x;
    if (e < E) {
        int s = edge_idx(ei, e);
        int d = edge_idx(ei, E + e);
        float w = g_dinv[s] * g_dinv[d];
        float2 f = USE_T ? g_t[s] : __ldg(&feat[s]);
        red_add_v2(&g_agg[d], f.x * w, f.y * w);
    }
}

// Per node: layer-1 epilogue (bias+relu), layer-2 down-projection, re-seed
// agg with t's self-loop term for the second aggregation.
__global__ void k_node_mid(const float* __restrict__ W1,
                           const float* __restrict__ b1,
                           const float* __restrict__ W2, int n) {
    int v = blockIdx.x * blockDim.x + threadIdx.x;
    if (v < n) {
        float2 a = g_agg[v];
        float t0 = 0.f, t1 = 0.f;
        #pragma unroll
        for (int j = 0; j < 16; j++) {
            float h = fmaf(a.x, __ldg(&W1[j]),
                      fmaf(a.y, __ldg(&W1[16 + j]), __ldg(&b1[j])));
            h = fmaxf(h, 0.f);
            t0 = fmaf(h, __ldg(&W2[2 * j]), t0);
            t1 = fmaf(h, __ldg(&W2[2 * j + 1]), t1);
        }
        float dv = g_dinv[v];
        float w = dv * dv;
        g_t[v] = make_float2(t0, t1);
        g_agg[v] = make_float2(t0 * w, t1 * w);
    }
}

__global__ void k_out(const float* __restrict__ b2, float2* __restrict__ out, int n) {
    int v = blockIdx.x * blockDim.x + threadIdx.x;
    if (v < n) {
        float2 a = g_agg[v];
        float v0 = a.x + __ldg(&b2[0]);
        float v1 = a.y + __ldg(&b2[1]);
        float m = fmaxf(v0, v1);
        float lse = m + logf(expf(v0 - m) + expf(v1 - m));
        out[v] = make_float2(v0 - lse, v1 - lse);
    }
}

extern "C" void kernel_launch(void* const* d_in, const int* in_sizes, int n_in,
                              void* d_out, int out_size) {
    const float2* x  = (const float2*)d_in[0];
    const void*   ei = d_in[1];                   // edge_index [2,E] (int32 or int64)
    const float*  W1 = (const float*)d_in[2];     // [2,16]
    const float*  b1 = (const float*)d_in[3];     // [16]
    const float*  W2 = (const float*)d_in[4];     // [16,2]
    const float*  b2 = (const float*)d_in[5];     // [2]

    int       n = in_sizes[0] / 2;
    long long E = (long long)in_sizes[1] / 2;

    const int TPB = 256;
    int nb_n = (n + TPB - 1) / TPB;
    int nb_e = (int)((E + TPB - 1) / TPB);

    k_detect    <<<1, 32>>>((const int*)ei, 2 * E);  // 2E int32 words safe either way
    k_zero_deg  <<<nb_n, TPB>>>(n);
    k_deg       <<<nb_e, TPB>>>(ei, E);
    k_dinv_init <<<nb_n, TPB>>>(x, n);
    k_edge<false><<<nb_e, TPB>>>(ei, x, E);
    k_node_mid  <<<nb_n, TPB>>>(W1, b1, W2, n);
    k_edge<true> <<<nb_e, TPB>>>(ei, nullptr, E);
    k_out       <<<nb_n, TPB>>>(b2, (float2*)d_out, n);
}

// round 13
// speedup vs baseline: 1.3403x; 1.3403x over previous
#include <cuda_runtime.h>
#include <cuda_bf16.h>

// GCN: out = log_softmax( GCN2( relu(GCN1(x)) ) ), Agg = D^-1/2 (A+I) D^-1/2.
//
// Algebraic restructurings:
//  (1) Linearity: aggregation commutes with the dense right-multiply, so both
//      layers aggregate 2-wide features (layer 2 down-projects BEFORE scatter).
//  (2) Normalization split: out[d] = dinv[d]*( sum_{s->d} (dinv[s]*f[s]) +
//      dinv[d]*f[d] ). Features pre-scaled by dinv at the nodes, result
//      post-scaled by dinv at the nodes -> edge kernel does NO dinv loads.
//
// The (possibly int64) edge index is converted ONCE per replay into packed
// int2 (src,dst) with degree counting fused in; both edge passes read
// 8B/edge of coalesced index.
//
// NOTE (R12 lesson): device-global arrays are referenced ONLY inside device
// code. Passing their "address" from host code hands the kernel the host-side
// shadow symbol, which GB300's ATS dereferences silently (zeros), corrupting
// results without a fault.
//
// Pipeline (7 kernels, graph-capturable, allocation-free):
//   K1 detect idx dtype + zero deg
//   K2 convert -> g_edge[int2], fused in-degree atomics
//   K3 node: dinv, xs = dinv*x, seed agg = xs
//   K4 edge1: agg[d] += xs[s]
//   K5 node: a=dinv*agg; t=relu(a@W1+b1)@W2; ts=dinv*t; g_t=ts; seed agg=ts
//   K6 edge2: agg[d] += ts[s]
//   K7 out = log_softmax(dinv*agg + b2)

#define MAXN 100352    // N_NODES = 100000, padded
#define MAXE 3276800   // E = 3200000, padded (even)

__device__ int      g_idx64;
__device__ unsigned g_deg[MAXN];
__device__ float    g_dinv[MAXN];
__device__ float2   g_xs[MAXN];
__device__ float2   g_t[MAXN];
__device__ float2   g_agg[MAXN];
__device__ int2     g_edge[MAXE];

__device__ __forceinline__ void red_add_v2(float2* addr, float a, float b) {
    // sm_90+ vector float reduction, fire-and-forget (no L2 return trip)
    asm volatile("red.global.add.v2.f32 [%0], {%1, %2};"
                 :: "l"(addr), "f"(a), "f"(b) : "memory");
}

// Detect index dtype (thread 0) + zero degree array (all threads).
// Samples 64 odd 32-bit words: int64 values < 2^31 have zero high halves;
// random int32 indices make the all-zero event ~1e-320.
__global__ void k_detect_zero(const int* __restrict__ ei32, long long n32, int n) {
    int v = blockIdx.x * blockDim.x + threadIdx.x;
    if (v < n) g_deg[v] = 0u;
    if (v == 0) {
        long long stride = n32 / 128;
        int all_zero = 1;
        for (int k = 0; k < 64; k++) {
            long long pos = 2 * (long long)k * stride + 1;
            if (pos < n32 && ei32[pos] != 0) { all_zero = 0; break; }
        }
        g_idx64 = all_zero;
    }
}

// Convert to packed int2 (coalesced 8B/edge for later passes) + fused degree.
__global__ void k_convert_deg(const void* __restrict__ ei, long long E) {
    long long e = (long long)blockIdx.x * blockDim.x + threadIdx.x;
    if (e < E) {
        int s, d;
        if (g_idx64) {
            const long long* p = (const long long*)ei;
            s = (int)p[e];
            d = (int)p[E + e];
        } else {
            const int* p = (const int*)ei;
            s = p[e];
            d = p[E + e];
        }
        g_edge[e] = make_int2(s, d);
        atomicAdd(&g_deg[d], 1u);
    }
}

// dinv = rsqrt(indeg+1); xs = dinv*x; seed agg = xs (self-loop term:
// final post-scale by dinv yields dinv^2 * x).
__global__ void k_node1(const float2* __restrict__ x, int n) {
    int v = blockIdx.x * blockDim.x + threadIdx.x;
    if (v < n) {
        float dv = rsqrtf((float)(g_deg[v] + 1u));
        g_dinv[v] = dv;
        float2 xv = x[v];
        float2 s = make_float2(xv.x * dv, xv.y * dv);
        g_xs[v] = s;
        g_agg[v] = s;
    }
}

// Minimal edge scatter: agg[dst] += feat[src], feat selected IN DEVICE CODE.
// 2 edges/thread via int4 index load.
template <bool USE_T>
__global__ void k_edge(long long E) {
    const float2* feat = USE_T ? g_t : g_xs;
    long long i = (long long)blockIdx.x * blockDim.x + threadIdx.x;
    long long e = 2 * i;
    if (e + 1 < E) {
        int4 sd = reinterpret_cast<const int4*>(g_edge)[i];
        float2 f0 = feat[sd.x];
        float2 f1 = feat[sd.z];
        red_add_v2(&g_agg[sd.y], f0.x, f0.y);
        red_add_v2(&g_agg[sd.w], f1.x, f1.y);
    } else if (e < E) {
        int2 sd = g_edge[e];
        float2 f = feat[sd.x];
        red_add_v2(&g_agg[sd.y], f.x, f.y);
    }
}

// Layer-1 epilogue + layer-2 down-projection + re-seed for second scatter.
__global__ void k_node_mid(const float* __restrict__ W1,
                           const float* __restrict__ b1,
                           const float* __restrict__ W2, int n) {
    int v = blockIdx.x * blockDim.x + threadIdx.x;
    if (v < n) {
        float dv = g_dinv[v];
        float2 g = g_agg[v];
        float ax = g.x * dv, ay = g.y * dv;   // finished layer-1 aggregation
        float t0 = 0.f, t1 = 0.f;
        #pragma unroll
        for (int j = 0; j < 16; j++) {
            float h = fmaf(ax, __ldg(&W1[j]),
                      fmaf(ay, __ldg(&W1[16 + j]), __ldg(&b1[j])));
            h = fmaxf(h, 0.f);
            t0 = fmaf(h, __ldg(&W2[2 * j]), t0);
            t1 = fmaf(h, __ldg(&W2[2 * j + 1]), t1);
        }
        float2 ts = make_float2(t0 * dv, t1 * dv);  // pre-scaled feature
        g_t[v] = ts;
        g_agg[v] = ts;                               // self-loop seed
    }
}

__global__ void k_out(const float* __restrict__ b2, float2* __restrict__ out, int n) {
    int v = blockIdx.x * blockDim.x + threadIdx.x;
    if (v < n) {
        float dv = g_dinv[v];
        float2 a = g_agg[v];
        float v0 = fmaf(a.x, dv, __ldg(&b2[0]));
        float v1 = fmaf(a.y, dv, __ldg(&b2[1]));
        float m = fmaxf(v0, v1);
        float lse = m + logf(expf(v0 - m) + expf(v1 - m));
        out[v] = make_float2(v0 - lse, v1 - lse);
    }
}

extern "C" void kernel_launch(void* const* d_in, const int* in_sizes, int n_in,
                              void* d_out, int out_size) {
    const float2* x  = (const float2*)d_in[0];
    const void*   ei = d_in[1];                   // edge_index [2,E] (int32/int64)
    const float*  W1 = (const float*)d_in[2];     // [2,16]
    const float*  b1 = (const float*)d_in[3];     // [16]
    const float*  W2 = (const float*)d_in[4];     // [16,2]
    const float*  b2 = (const float*)d_in[5];     // [2]

    int       n = in_sizes[0] / 2;
    long long E = (long long)in_sizes[1] / 2;

    const int TPB = 256;
    int nb_n = (n + TPB - 1) / TPB;
    int nb_e = (int)((E + TPB - 1) / TPB);
    long long half = (E + 1) / 2;
    int nb_e2 = (int)((half + TPB - 1) / TPB);

    k_detect_zero  <<<nb_n, TPB>>>((const int*)ei, 2 * E, n);
    k_convert_deg  <<<nb_e, TPB>>>(ei, E);
    k_node1        <<<nb_n, TPB>>>(x, n);
    k_edge<false>  <<<nb_e2, TPB>>>(E);
    k_node_mid     <<<nb_n, TPB>>>(W1, b1, W2, n);
    k_edge<true>   <<<nb_e2, TPB>>>(E);
    k_out          <<<nb_n, TPB>>>(b2, (float2*)d_out, n);
}